// round 6
// baseline (speedup 1.0000x reference)
#include <cuda_runtime.h>

// Problem constants
#define BATCH 2
#define DD 160
#define HH 160
#define WW 160
#define NTOT (BATCH * DD * HH * WW)   // 8192000
#define INV125 (1.0f / 125.0f)

// Tile config
#define TW 32               // tile width (voxels)
#define TPC 16              // pair-columns (TW/2), threadIdx.x
#define TH 16               // tile height, threadIdx.y
#define DCH 40              // depth chunk per block  -> 400 blocks
#define NCHUNK (DD / DCH)   // 4
#define NTHR 256
#define SROWS (TH + 4)      // 20
#define SCOLS (TW + 4)      // 36
#define SCOLSP 37           // odd padding: conflict-free cross-row access
#define SELEMS (SROWS * SCOLS)  // 720

__global__ void __launch_bounds__(NTHR)
lncc_fused(const float* __restrict__ M,
           const float* __restrict__ R,
           float* __restrict__ out) {
    __shared__ float sm[SROWS][SCOLSP];
    __shared__ float sr[SROWS][SCOLSP];
    __shared__ float tmp[5][SROWS][TW];

    const int tx  = threadIdx.x;          // 0..15 (pair col)
    const int ty  = threadIdx.y;          // 0..15 (row)
    const int tid = ty * TPC + tx;        // 0..255
    const int x2  = 2 * tx;

    const int w0 = blockIdx.x * TW;
    const int h0 = blockIdx.y * TH;
    const int bz = blockIdx.z;            // b*NCHUNK + chunk
    const int b  = bz >> 2;               // NCHUNK == 4
    const int z0 = (bz & 3) * DCH;

    const size_t vol = (size_t)HH * WW;
    const float* Mb = M + (size_t)b * DD * vol;
    const float* Rb = R + (size_t)b * DD * vol;

    // ---- Loop-invariant staging metadata (32-bit offsets, low reg cost) ----
    int  goff[3], soff[3];
    bool vld[3], inb[3];
#pragma unroll
    for (int k = 0; k < 3; k++) {
        const int i = tid + k * NTHR;
        vld[k] = (i < SELEMS);
        int row = 0, col = 0, h = 0, w = 0;
        if (vld[k]) {
            row = i / SCOLS;
            col = i - row * SCOLS;
            h = h0 - 2 + row;
            w = w0 - 2 + col;
        }
        const bool ok = vld[k] & ((unsigned)h < HH) & ((unsigned)w < WW);
        inb[k]  = ok;
        goff[k] = ok ? (h * WW + w) : 0;
        soff[k] = row * SCOLSP + col;
    }

    // Depth ring + running sums, fully in registers (static indexing).
    float2 ring[5][5];   // [field][phase]
    float2 runs[5];
#pragma unroll
    for (int f = 0; f < 5; f++) {
        runs[f] = make_float2(0.f, 0.f);
#pragma unroll
        for (int j = 0; j < 5; j++) ring[f][j] = make_float2(0.f, 0.f);
    }

    float acc = 0.f;

    // ---- Prefetch first plane (z0-2) ----
    float pm[3], pr[3];
    {
        const int z = z0 - 2;
        const bool okz = (z >= 0);
#pragma unroll
        for (int k = 0; k < 3; k++) {
            float mv = 0.f, rv = 0.f;
            if (okz & inb[k]) {
                const size_t g = (size_t)z * vol + goff[k];
                mv = Mb[g]; rv = Rb[g];
            }
            pm[k] = mv; pr[k] = rv;
        }
    }

    float* const smf = &sm[0][0];
    float* const srf = &sr[0][0];

    for (int sb = 0; sb < 45; sb += 5) {
#pragma unroll
        for (int ph = 0; ph < 5; ph++) {
            const int s = sb + ph;
            if (s < 44) {               // uniform guard (pad iteration skipped)
                // ---- Commit prefetched plane to staging ----
#pragma unroll
                for (int k = 0; k < 3; k++)
                    if (vld[k]) { smf[soff[k]] = pm[k]; srf[soff[k]] = pr[k]; }
                __syncthreads();

                // ---- Prefetch next plane (latency hidden by stages 2+3) ----
                {
                    const int z = z0 - 1 + s;
                    const bool okz = ((unsigned)z < DD) & (s < 43);
#pragma unroll
                    for (int k = 0; k < 3; k++) {
                        float mv = 0.f, rv = 0.f;
                        if (okz & inb[k]) {
                            const size_t g = (size_t)z * vol + goff[k];
                            mv = Mb[g]; rv = Rb[g];
                        }
                        pm[k] = mv; pr[k] = rv;
                    }
                }

                // ---- Stage 2: W-filter 5 products (320 positions) ----
                auto do_pos = [&](int i) {
                    const int row = i >> 4;
                    const int pc  = i & 15;
                    const int xb  = 2 * pc;
                    float m_[6], r_[6];
#pragma unroll
                    for (int k = 0; k < 6; k++) {
                        m_[k] = sm[row][xb + k];
                        r_[k] = sr[row][xb + k];
                    }
                    float aM0 = 0.f, aR0 = 0.f, aMM0 = 0.f, aRR0 = 0.f, aMR0 = 0.f;
                    float aM1 = 0.f, aR1 = 0.f, aMM1 = 0.f, aRR1 = 0.f, aMR1 = 0.f;
#pragma unroll
                    for (int k = 0; k < 5; k++) {
                        aM0 += m_[k];  aR0 += r_[k];
                        aMM0 = fmaf(m_[k], m_[k], aMM0);
                        aRR0 = fmaf(r_[k], r_[k], aRR0);
                        aMR0 = fmaf(m_[k], r_[k], aMR0);
                        aM1 += m_[k+1]; aR1 += r_[k+1];
                        aMM1 = fmaf(m_[k+1], m_[k+1], aMM1);
                        aRR1 = fmaf(r_[k+1], r_[k+1], aRR1);
                        aMR1 = fmaf(m_[k+1], r_[k+1], aMR1);
                    }
                    *(float2*)&tmp[0][row][xb] = make_float2(aM0,  aM1);
                    *(float2*)&tmp[1][row][xb] = make_float2(aR0,  aR1);
                    *(float2*)&tmp[2][row][xb] = make_float2(aMM0, aMM1);
                    *(float2*)&tmp[3][row][xb] = make_float2(aRR0, aRR1);
                    *(float2*)&tmp[4][row][xb] = make_float2(aMR0, aMR1);
                };
                do_pos(tid);
                if (tid < SROWS * TPC - NTHR) do_pos(tid + NTHR);
                __syncthreads();

                // ---- Stage 3: H-filter + register-ring D update ----
#pragma unroll
                for (int f = 0; f < 5; f++) {
                    float vx = 0.f, vy = 0.f;
#pragma unroll
                    for (int j = 0; j < 5; j++) {
                        const float2 t = *(const float2*)&tmp[f][ty + j][x2];
                        vx += t.x; vy += t.y;
                    }
                    const float2 o = ring[f][ph];      // static reg access
                    runs[f].x += vx - o.x;
                    runs[f].y += vy - o.y;
                    ring[f][ph] = make_float2(vx, vy);
                }

                // ---- Stage 4: emit output plane zout = zin - 2 ----
                if (s >= 4) {
#pragma unroll
                    for (int c = 0; c < 2; c++) {
                        const float Mm  = (c ? runs[0].y : runs[0].x) * INV125;
                        const float Rm  = (c ? runs[1].y : runs[1].x) * INV125;
                        const float MMm = (c ? runs[2].y : runs[2].x) * INV125;
                        const float RRm = (c ? runs[3].y : runs[3].x) * INV125;
                        const float MRm = (c ? runs[4].y : runs[4].x) * INV125;

                        const float a   = fmaf(-Mm, Mm, MMm) + 1e-5f;
                        const float bb  = fmaf(-Rm, Rm, RRm) + 1e-5f;
                        const float num = fmaf(-Mm, Rm, MRm);
                        const float ab  = a * bb;
                        const float den = ab * rsqrtf(ab) + 1e-5f;
                        acc += __fdividef(num, den);
                    }
                }
            }
        }
    }

    // ---- Block reduction (256 threads) + atomic ----
    __shared__ float warp_sums[NTHR / 32];
    float v = acc;
#pragma unroll
    for (int off = 16; off > 0; off >>= 1)
        v += __shfl_xor_sync(0xFFFFFFFFu, v, off);
    if ((tid & 31) == 0) warp_sums[tid >> 5] = v;
    __syncthreads();
    if (tid < 32) {
        float sWS = (tid < NTHR / 32) ? warp_sums[tid] : 0.f;
#pragma unroll
        for (int off = 4; off > 0; off >>= 1)
            sWS += __shfl_xor_sync(0xFFFFFFFFu, sWS, off);
        if (tid == 0)
            atomicAdd(out, -sWS * (1.0f / (float)NTOT));
    }
}

__global__ void lncc_zero_out(float* out) { out[0] = 0.f; }

// ---------------------------------------------------------------------------
extern "C" void kernel_launch(void* const* d_in, const int* in_sizes, int n_in,
                              void* d_out, int out_size) {
    const float* M = (const float*)d_in[0];
    const float* R = (const float*)d_in[1];
    // d_in[2] is the box kernel (ones/125) — folded into INV125.
    float* out = (float*)d_out;

    lncc_zero_out<<<1, 1>>>(out);

    dim3 blk(TPC, TH, 1);                                   // (16,16) = 256
    dim3 grd(WW / TW, HH / TH, BATCH * NCHUNK);             // (5,10,8) = 400
    lncc_fused<<<grd, blk>>>(M, R, out);
}

// round 7
// speedup vs baseline: 1.1096x; 1.1096x over previous
#include <cuda_runtime.h>

// Problem constants
#define BATCH 2
#define DD 160
#define HH 160
#define WW 160
#define NTOT (BATCH * DD * HH * WW)   // 8192000
#define INV125 (1.0f / 125.0f)

// Tile config
#define TW 32               // tile width (voxels)
#define TPC 16              // pair-columns (TW/2), threadIdx.x
#define TH 16               // tile height, threadIdx.y
#define DCH 40              // depth chunk per block  -> 400 blocks
#define NCHUNK (DD / DCH)   // 4
#define NTHR 256
#define SROWS (TH + 4)      // 20
#define SCOLS (TW + 4)      // 36
#define SCOLSP 38           // float2 stride: even -> every row 16B-aligned
#define SELEMS (SROWS * SCOLS)  // 720

__global__ void __launch_bounds__(NTHR, 3)
lncc_fused(const float* __restrict__ M,
           const float* __restrict__ R,
           float* __restrict__ out) {
    // Staging: interleaved (m, r) pairs.
    __shared__ float2 mr[SROWS][SCOLSP];                 // 6.08 KB
    // W-filtered fields, packed 2 per float4 (x,y = col pair of field A;
    // z,w = col pair of field B).
    __shared__ float4 tmpa[SROWS][TPC];                  // {M0,M1,R0,R1}
    __shared__ float4 tmpb[SROWS][TPC];                  // {MM0,MM1,RR0,RR1}
    __shared__ float2 tmpc[SROWS][TPC];                  // {MR0,MR1}
    // Depth ring (5 planes of HW-filtered sums), same packing.
    __shared__ float4 hista[5][TH][TPC];
    __shared__ float4 histb[5][TH][TPC];
    __shared__ float2 histc[5][TH][TPC];

    const int tx  = threadIdx.x;          // 0..15 (pair col)
    const int ty  = threadIdx.y;          // 0..15 (row)
    const int tid = ty * TPC + tx;        // 0..255

    const int w0 = blockIdx.x * TW;
    const int h0 = blockIdx.y * TH;
    const int bz = blockIdx.z;            // b*NCHUNK + chunk
    const int b  = bz >> 2;               // NCHUNK == 4
    const int z0 = (bz & 3) * DCH;

    const size_t vol = (size_t)HH * WW;
    const float* Mb = M + (size_t)b * DD * vol;
    const float* Rb = R + (size_t)b * DD * vol;

    // ---- Loop-invariant staging metadata ----
    int  goff[3], soff[3];
    bool vld[3], inb[3];
#pragma unroll
    for (int k = 0; k < 3; k++) {
        const int i = tid + k * NTHR;
        vld[k] = (i < SELEMS);
        int row = 0, col = 0, h = 0, w = 0;
        if (vld[k]) {
            row = i / SCOLS;
            col = i - row * SCOLS;
            h = h0 - 2 + row;
            w = w0 - 2 + col;
        }
        const bool ok = vld[k] & ((unsigned)h < HH) & ((unsigned)w < WW);
        inb[k]  = ok;
        goff[k] = ok ? (h * WW + w) : 0;
        soff[k] = row * SCOLSP + col;
    }

    // Zero own ring slots (thread-private; no barrier needed).
#pragma unroll
    for (int j = 0; j < 5; j++) {
        hista[j][ty][tx] = make_float4(0.f, 0.f, 0.f, 0.f);
        histb[j][ty][tx] = make_float4(0.f, 0.f, 0.f, 0.f);
        histc[j][ty][tx] = make_float2(0.f, 0.f);
    }

    // Running D-window sums, in registers.
    float4 runs_ab = make_float4(0.f, 0.f, 0.f, 0.f);   // {M0,M1,R0,R1}
    float4 runs_cd = make_float4(0.f, 0.f, 0.f, 0.f);   // {MM0,MM1,RR0,RR1}
    float2 runs_e  = make_float2(0.f, 0.f);             // {MR0,MR1}

    float acc = 0.f;
    int rp = 0;

    // ---- Prefetch first plane (z0-2) ----
    float pm[3], pr[3];
    {
        const int z = z0 - 2;
        const bool okz = (z >= 0);
#pragma unroll
        for (int k = 0; k < 3; k++) {
            float mv = 0.f, rv = 0.f;
            if (okz & inb[k]) {
                const size_t g = (size_t)z * vol + goff[k];
                mv = Mb[g]; rv = Rb[g];
            }
            pm[k] = mv; pr[k] = rv;
        }
    }

    float2* const mrf = &mr[0][0];

    for (int s = 0; s < DCH + 4; s++) {
        // ---- Commit prefetched plane to staging ----
#pragma unroll
        for (int k = 0; k < 3; k++)
            if (vld[k]) mrf[soff[k]] = make_float2(pm[k], pr[k]);
        __syncthreads();

        // ---- Prefetch next plane (latency hidden by stages 2+3) ----
        {
            const int z = z0 - 1 + s;
            const bool okz = ((unsigned)z < DD);
#pragma unroll
            for (int k = 0; k < 3; k++) {
                float mv = 0.f, rv = 0.f;
                if (okz & inb[k]) {
                    const size_t g = (size_t)z * vol + goff[k];
                    mv = Mb[g]; rv = Rb[g];
                }
                pm[k] = mv; pr[k] = rv;
            }
        }

        // ---- Stage 2: W-filter 5 products (320 positions, wide LDS) ----
        auto do_pos = [&](int i) {
            const int row = i >> 4;
            const int pc  = i & 15;
            const int xb  = 2 * pc;
            const float4 q0 = *(const float4*)&mr[row][xb];      // m0 r0 m1 r1
            const float4 q1 = *(const float4*)&mr[row][xb + 2];  // m2 r2 m3 r3
            const float4 q2 = *(const float4*)&mr[row][xb + 4];  // m4 r4 m5 r5
            const float m0 = q0.x, r0 = q0.y, m1 = q0.z, r1 = q0.w;
            const float m2 = q1.x, r2 = q1.y, m3 = q1.z, r3 = q1.w;
            const float m4 = q2.x, r4 = q2.y, m5 = q2.z, r5 = q2.w;

            // shared 4-tap partials (cols 1..4)
            const float tM  = m1 + m2 + m3 + m4;
            const float tR  = r1 + r2 + r3 + r4;
            const float tMM = fmaf(m1, m1, fmaf(m2, m2, fmaf(m3, m3, m4 * m4)));
            const float tRR = fmaf(r1, r1, fmaf(r2, r2, fmaf(r3, r3, r4 * r4)));
            const float tMR = fmaf(m1, r1, fmaf(m2, r2, fmaf(m3, r3, m4 * r4)));

            tmpa[row][pc] = make_float4(tM + m0, tM + m5, tR + r0, tR + r5);
            tmpb[row][pc] = make_float4(fmaf(m0, m0, tMM), fmaf(m5, m5, tMM),
                                        fmaf(r0, r0, tRR), fmaf(r5, r5, tRR));
            tmpc[row][pc] = make_float2(fmaf(m0, r0, tMR), fmaf(m5, r5, tMR));
        };
        do_pos(tid);
        if (tid < SROWS * TPC - NTHR) do_pos(tid + NTHR);
        __syncthreads();

        // ---- Stage 3: H-filter (wide taps) + smem-ring D update ----
        {
            float4 s_ab = make_float4(0.f, 0.f, 0.f, 0.f);
            float4 s_cd = make_float4(0.f, 0.f, 0.f, 0.f);
            float2 s_e  = make_float2(0.f, 0.f);
#pragma unroll
            for (int j = 0; j < 5; j++) {
                const float4 a = tmpa[ty + j][tx];
                const float4 c = tmpb[ty + j][tx];
                const float2 e = tmpc[ty + j][tx];
                s_ab.x += a.x; s_ab.y += a.y; s_ab.z += a.z; s_ab.w += a.w;
                s_cd.x += c.x; s_cd.y += c.y; s_cd.z += c.z; s_cd.w += c.w;
                s_e.x  += e.x; s_e.y  += e.y;
            }
            const float4 oa = hista[rp][ty][tx];
            const float4 ob = histb[rp][ty][tx];
            const float2 oc = histc[rp][ty][tx];
            runs_ab.x += s_ab.x - oa.x; runs_ab.y += s_ab.y - oa.y;
            runs_ab.z += s_ab.z - oa.z; runs_ab.w += s_ab.w - oa.w;
            runs_cd.x += s_cd.x - ob.x; runs_cd.y += s_cd.y - ob.y;
            runs_cd.z += s_cd.z - ob.z; runs_cd.w += s_cd.w - ob.w;
            runs_e.x  += s_e.x  - oc.x; runs_e.y  += s_e.y  - oc.y;
            hista[rp][ty][tx] = s_ab;
            histb[rp][ty][tx] = s_cd;
            histc[rp][ty][tx] = s_e;
        }

        rp = (rp == 4) ? 0 : rp + 1;

        // ---- Stage 4: emit output plane zout = zin - 2 ----
        if (s >= 4) {
#pragma unroll
            for (int c = 0; c < 2; c++) {
                const float Mm  = (c ? runs_ab.y : runs_ab.x) * INV125;
                const float Rm  = (c ? runs_ab.w : runs_ab.z) * INV125;
                const float MMm = (c ? runs_cd.y : runs_cd.x) * INV125;
                const float RRm = (c ? runs_cd.w : runs_cd.z) * INV125;
                const float MRm = (c ? runs_e.y  : runs_e.x ) * INV125;

                const float a   = fmaf(-Mm, Mm, MMm) + 1e-5f;
                const float bb  = fmaf(-Rm, Rm, RRm) + 1e-5f;
                const float num = fmaf(-Mm, Rm, MRm);
                const float ab  = a * bb;
                const float den = ab * rsqrtf(ab) + 1e-5f;  // sqrt(a)*sqrt(b)+eps
                acc += __fdividef(num, den);
            }
        }
    }

    // ---- Block reduction (256 threads) + atomic ----
    __shared__ float warp_sums[NTHR / 32];
    float v = acc;
#pragma unroll
    for (int off = 16; off > 0; off >>= 1)
        v += __shfl_xor_sync(0xFFFFFFFFu, v, off);
    if ((tid & 31) == 0) warp_sums[tid >> 5] = v;
    __syncthreads();
    if (tid < 32) {
        float sWS = (tid < NTHR / 32) ? warp_sums[tid] : 0.f;
#pragma unroll
        for (int off = 4; off > 0; off >>= 1)
            sWS += __shfl_xor_sync(0xFFFFFFFFu, sWS, off);
        if (tid == 0)
            atomicAdd(out, -sWS * (1.0f / (float)NTOT));
    }
}

__global__ void lncc_zero_out(float* out) { out[0] = 0.f; }

// ---------------------------------------------------------------------------
extern "C" void kernel_launch(void* const* d_in, const int* in_sizes, int n_in,
                              void* d_out, int out_size) {
    const float* M = (const float*)d_in[0];
    const float* R = (const float*)d_in[1];
    // d_in[2] is the box kernel (ones/125) — folded into INV125.
    float* out = (float*)d_out;

    lncc_zero_out<<<1, 1>>>(out);

    dim3 blk(TPC, TH, 1);                                   // (16,16) = 256
    dim3 grd(WW / TW, HH / TH, BATCH * NCHUNK);             // (5,10,8) = 400
    lncc_fused<<<grd, blk>>>(M, R, out);
}